// round 1
// baseline (speedup 1.0000x reference)
#include <cuda_runtime.h>

#define BB   16
#define NN   512
#define MM   1024
#define CIN  7
#define CC   8
#define COUT 64
#define TM   128   // m-values (=threads) per block

__device__ __forceinline__ float ex2f(float x) {
    float y;
    asm("ex2.approx.ftz.f32 %0, %1;" : "=f"(y) : "f"(x));
    return y;
}

__global__ __launch_bounds__(TM)
void convdeepset_kernel(const float* __restrict__ ci,   // (B,N,1)
                        const float* __restrict__ co,   // (B,N,CIN)
                        const float* __restrict__ ti,   // (B,M,1)
                        const float* __restrict__ sigma,// (C,)
                        const float* __restrict__ W,    // (COUT,C)
                        const float* __restrict__ bias, // (COUT,)
                        float* __restrict__ out)        // (B,M,COUT)
{
    __shared__ float4 s_ctx[NN * 2];      // per n: [x, c0, c1, c2], [c3, c4, c5, c6]
    __shared__ float  s_Wt[CC][COUT];     // W transposed: [c][o]
    __shared__ float  s_bias[COUT];
    __shared__ float  s_k2[CC];           // -0.5*log2(e)/scale_c^2
    __shared__ int    s_uniform;

    const int tid = threadIdx.x;
    const int blk = blockIdx.x;
    const int b   = blk / (MM / TM);
    const int mt  = blk % (MM / TM);
    const int m   = mt * TM + tid;

    if (tid < CC) {
        float s = sigma[tid];
        // exp(-0.5*d/scale^2) = exp2(d * k2),  k2 = -0.5*log2e*exp(-2*sigma)
        s_k2[tid] = -0.5f * 1.4426950408889634f * expf(-2.0f * s);
    }
    if (tid == 0) {
        int u = 1;
        float s0 = sigma[0];
        #pragma unroll
        for (int c = 1; c < CC; c++) u &= (sigma[c] == s0);
        s_uniform = u;
    }
    // W transposed into smem (conflict-free epilogue reads)
    for (int i = tid; i < CC * COUT; i += TM) {
        int o = i / CC, c = i % CC;
        s_Wt[c][o] = W[i];
    }
    if (tid < COUT) s_bias[tid] = bias[tid];

    // stage context rows for this batch
    const float* cib = ci + (size_t)b * NN;
    const float* cob = co + (size_t)b * NN * CIN;
    for (int i = tid; i < NN; i += TM) {
        float4 a, bb;
        a.x  = cib[i];
        a.y  = cob[i * CIN + 0];
        a.z  = cob[i * CIN + 1];
        a.w  = cob[i * CIN + 2];
        bb.x = cob[i * CIN + 3];
        bb.y = cob[i * CIN + 4];
        bb.z = cob[i * CIN + 5];
        bb.w = cob[i * CIN + 6];
        s_ctx[2 * i]     = a;
        s_ctx[2 * i + 1] = bb;
    }
    __syncthreads();

    const float t = ti[(size_t)b * MM + m];

    float acc[CC];
    #pragma unroll
    for (int c = 0; c < CC; c++) acc[c] = 0.0f;

    if (s_uniform) {
        // ---- fast path: one exp per (n,m) ----
        const float k2 = s_k2[0];
        #pragma unroll 4
        for (int n = 0; n < NN; n++) {
            float4 a  = s_ctx[2 * n];
            float4 bb = s_ctx[2 * n + 1];
            float diff = a.x - t;
            float w = ex2f(diff * diff * k2);
            acc[0] += w;
            acc[1] += w * a.y;
            acc[2] += w * a.z;
            acc[3] += w * a.w;
            acc[4] += w * bb.x;
            acc[5] += w * bb.y;
            acc[6] += w * bb.z;
            acc[7] += w * bb.w;
        }
    } else {
        // ---- general path: per-channel scales ----
        float k2[CC];
        #pragma unroll
        for (int c = 0; c < CC; c++) k2[c] = s_k2[c];
        #pragma unroll 2
        for (int n = 0; n < NN; n++) {
            float4 a  = s_ctx[2 * n];
            float4 bb = s_ctx[2 * n + 1];
            float diff = a.x - t;
            float d = diff * diff;
            acc[0] += ex2f(d * k2[0]);
            acc[1] += ex2f(d * k2[1]) * a.y;
            acc[2] += ex2f(d * k2[2]) * a.z;
            acc[3] += ex2f(d * k2[3]) * a.w;
            acc[4] += ex2f(d * k2[4]) * bb.x;
            acc[5] += ex2f(d * k2[5]) * bb.y;
            acc[6] += ex2f(d * k2[6]) * bb.z;
            acc[7] += ex2f(d * k2[7]) * bb.w;
        }
    }

    // epilogue: density normalize + fused (8 -> 64) GEMM + bias
    float v[CC];
    float inv = 1.0f / (acc[0] + 1e-8f);
    v[0] = acc[0];
    #pragma unroll
    for (int c = 1; c < CC; c++) v[c] = acc[c] * inv;

    float4* outp = (float4*)(out + ((size_t)(b * MM + m)) * COUT);
    #pragma unroll
    for (int o4 = 0; o4 < COUT / 4; o4++) {
        const float4* bsp = (const float4*)&s_bias[o4 * 4];
        float4 r = *bsp;
        #pragma unroll
        for (int c = 0; c < CC; c++) {
            const float4 w4 = *(const float4*)&s_Wt[c][o4 * 4];
            r.x += v[c] * w4.x;
            r.y += v[c] * w4.y;
            r.z += v[c] * w4.z;
            r.w += v[c] * w4.w;
        }
        outp[o4] = r;
    }
}

extern "C" void kernel_launch(void* const* d_in, const int* in_sizes, int n_in,
                              void* d_out, int out_size) {
    const float* ci    = (const float*)d_in[0];
    const float* co    = (const float*)d_in[1];
    const float* ti    = (const float*)d_in[2];
    const float* sigma = (const float*)d_in[3];
    const float* W     = (const float*)d_in[4];
    const float* bias  = (const float*)d_in[5];
    float* out = (float*)d_out;

    dim3 grid(BB * MM / TM);   // 128 blocks
    dim3 block(TM);            // 128 threads
    convdeepset_kernel<<<grid, block>>>(ci, co, ti, sigma, W, bias, out);
}